// round 2
// baseline (speedup 1.0000x reference)
#include <cuda_runtime.h>

// Occupancy connectivity loss over a 385^3 fp32 grid, C order:
//   f = x*385^2 + y*385 + z
// Strategy: warp owns (y, 128-wide z segment), loops over an x-chunk.
//   x-diff: previous iteration's registers (no load)
//   z-diff: __shfl_down within the warp (no load)
//   y-diff: one coalesced row load at +ROW
// All loads are lane-contiguous LDG.32 -> 1 L1 wavefront per 128B.

#define ROW    385u
#define PLANE  148225u
#define NSEG   3
#define XCHUNKS 5
#define XSTEP  77u
#define NTASKS (385 * NSEG * XCHUNKS)   // 5775 warp-tasks
#define WPB    8                        // warps per block (256 threads)
#define NBLOCKS ((NTASKS + WPB - 1) / WPB)  // 722

__device__ double g_part[NBLOCKS];

__global__ void __launch_bounds__(256) occ_main(const float* __restrict__ occ) {
    const unsigned wid  = threadIdx.x >> 5;
    const unsigned lane = threadIdx.x & 31u;
    const unsigned task = blockIdx.x * WPB + wid;

    float s = 0.0f;

    if (task < NTASKS) {
        // y fastest so adjacent-y tasks are launched together (L2 reuse of
        // the y-neighbor row).
        const unsigned y   = task % 385u;
        const unsigned t2  = task / 385u;
        const unsigned seg = t2 % NSEG;     // z segment: 0..2
        const unsigned xc  = t2 / NSEG;     // x chunk:   0..4
        const unsigned zb  = seg * 128u;
        const unsigned xs  = xc * XSTEP;
        const unsigned xe  = xs + XSTEP;          // y/z-diffs for x in [xs, xe)
        const unsigned xlast = (xe < 384u) ? xe : 384u;  // inclusive loop bound
        const bool havey = (y < 384u);
        const bool s2    = (seg == 2u);           // segment owning z=384 halo

        const float* base = occ + (size_t)y * ROW + zb + lane;

        float vp0 = 0.f, vp1 = 0.f, vp2 = 0.f, vp3 = 0.f, hcprev = 0.f;

        for (unsigned x = xs; x <= xlast; ++x) {
            const float* p = base + (size_t)x * PLANE;
            // coalesced center loads: z = zb + 32*j + lane
            float v0 = __ldg(p);
            float v1 = __ldg(p + 32);
            float v2 = __ldg(p + 64);
            float v3 = __ldg(p + 96);
            // halo element z = zb + 128 (always <= 384)
            float hc = 0.f;
            if (lane == 0u) hc = __ldg(p + 128);
            hc = __shfl_sync(0xffffffffu, hc, 0);

            if (x > xs) {
                // x-diffs for pair (x-1, x)
                s += fabsf(v0 - vp0) + fabsf(v1 - vp1)
                   + fabsf(v2 - vp2) + fabsf(v3 - vp3);
                if (s2 && lane == 0u) s += fabsf(hc - hcprev);  // z=384 column
            }

            if (x < xe) {
                // z-diffs: neighbor z+1 via shuffle
                float n0 = __shfl_down_sync(0xffffffffu, v0, 1);
                float n1 = __shfl_down_sync(0xffffffffu, v1, 1);
                float n2 = __shfl_down_sync(0xffffffffu, v2, 1);
                float n3 = __shfl_down_sync(0xffffffffu, v3, 1);
                float b1 = __shfl_sync(0xffffffffu, v1, 0);
                float b2 = __shfl_sync(0xffffffffu, v2, 0);
                float b3 = __shfl_sync(0xffffffffu, v3, 0);
                if (lane == 31u) { n0 = b1; n1 = b2; n2 = b3; n3 = hc; }
                s += fabsf(n0 - v0) + fabsf(n1 - v1)
                   + fabsf(n2 - v2) + fabsf(n3 - v3);

                if (havey) {
                    // y-diffs: coalesced row at +ROW (L2 hit: it is the
                    // center row of the adjacent-y task)
                    const float* q = p + ROW;
                    s += fabsf(__ldg(q)      - v0) + fabsf(__ldg(q + 32) - v1)
                       + fabsf(__ldg(q + 64) - v2) + fabsf(__ldg(q + 96) - v3);
                    if (s2 && lane == 0u)
                        s += fabsf(__ldg(q + 128) - hc);        // z=384 column
                }
            }

            vp0 = v0; vp1 = v1; vp2 = v2; vp3 = v3; hcprev = hc;
        }
    }

    // ---- reduce block -> one double partial (plain store, no zero pass) ----
    #pragma unroll
    for (int o = 16; o > 0; o >>= 1)
        s += __shfl_down_sync(0xffffffffu, s, o);

    __shared__ float ws[WPB];
    if (lane == 0u) ws[wid] = s;
    __syncthreads();
    if (threadIdx.x == 0u) {
        float t = 0.f;
        #pragma unroll
        for (int i = 0; i < WPB; ++i) t += ws[i];
        g_part[blockIdx.x] = (double)t;
    }
}

__global__ void occ_finalize(float* __restrict__ out) {
    double s = 0.0;
    for (unsigned i = threadIdx.x; i < NBLOCKS; i += 256u)
        s += g_part[i];

    __shared__ double sm[256];
    sm[threadIdx.x] = s;
    __syncthreads();
    #pragma unroll
    for (int st = 128; st > 0; st >>= 1) {
        if ((int)threadIdx.x < st) sm[threadIdx.x] += sm[threadIdx.x + st];
        __syncthreads();
    }
    if (threadIdx.x == 0u) out[0] = (float)sm[0];
}

extern "C" void kernel_launch(void* const* d_in, const int* in_sizes, int n_in,
                              void* d_out, int out_size) {
    const float* occ = (const float*)d_in[0];
    float* out = (float*)d_out;

    occ_main<<<NBLOCKS, 256>>>(occ);
    occ_finalize<<<1, 256>>>(out);
}

// round 4
// speedup vs baseline: 1.2025x; 1.2025x over previous
#include <cuda_runtime.h>

// Occupancy connectivity loss over a 385^3 fp32 grid, C order:
//   f = x*385^2 + y*385 + z
// Single-read design: block = 8 warps = 8 consecutive y-rows of a 128-wide
// z segment (+1 halo col), marching over an x chunk. Per x-plane each warp
// loads its row ONCE as 4 coalesced LDG.32 (+ lane31 halo scalar):
//   x-diff: previous iteration's registers
//   z-diff: smem[idx+1] vs register (halo column handled naturally)
//   y-diff: neighbor warp's row via double-buffered shared memory
// Rows loaded 8, owned 7 (8th row is halo for the next y-group).
// NO float4 on global: ROW=385 and PLANE=148225 are odd -> rows unaligned.

#define ROW    385u
#define PLANE  148225u
#define WPB    8u          // warps per block
#define OWN    7u          // rows owned per block (8th is halo)
#define NYG    55u         // 55*7 = 385 rows
#define XC     5u          // x chunks
#define NZSEG  3u          // z segments of 128 (+ shared halo column)
#define NBLOCKS (NZSEG * NYG * XC)   // 825

__device__ double   g_part[NBLOCKS];
__device__ unsigned g_count = 0;

__global__ void __launch_bounds__(256, 6)
occ_main(const float* __restrict__ occ, float* __restrict__ out) {
    const unsigned wid  = threadIdx.x >> 5;
    const unsigned lane = threadIdx.x & 31u;

    const unsigned zseg = blockIdx.x % NZSEG;
    const unsigned rest = blockIdx.x / NZSEG;
    const unsigned xc   = rest % XC;
    const unsigned g    = rest / XC;

    const unsigned zb    = zseg * 128u;
    const unsigned yb    = g * OWN;
    const unsigned nload = min(WPB, 385u - yb);   // 8 (7 for last group)
    const unsigned nown  = min(OWN, 385u - yb);   // 7
    const unsigned y     = yb + wid;
    const bool rowload = (wid < nload);
    const bool rowown  = (wid < nown);
    const bool ypair   = rowown && (y < 384u);
    const bool halo31  = (zseg == 2u) && (lane == 31u); // z=384 col x/y diffs

    const unsigned as = (384u * xc) / XC;         // own x-pairs [as, ae)
    const unsigned ae = (384u * (xc + 1u)) / XC;  // y/z diffs x in [as,ae) (+384 if last)
    const bool lastc = (ae == 384u);

    __shared__ float sm[2][WPB][132];             // [buf][row][z(128)+halo+pad]

    // coalesced scalar bases: z = zb + lane + 32*j
    const float* rowp = occ + (size_t)y * ROW + zb + lane;

    float s = 0.0f;
    float v0=0.f,v1=0.f,v2=0.f,v3=0.f, p0=0.f,p1=0.f,p2=0.f,p3=0.f;
    float hc = 0.f, hp = 0.f;

    if (rowload) {
        const float* p = rowp + (size_t)as * PLANE;
        v0 = __ldg(p);      v1 = __ldg(p + 32);
        v2 = __ldg(p + 64); v3 = __ldg(p + 96);
        if (lane == 31u) hc = __ldg(p + 97);      // z = zb+128 halo
    }

    unsigned buf = 0u;
    for (unsigned x = as; x <= ae; ++x) {
        // publish current plane row to smem
        if (rowload) {
            float* r = sm[buf][wid];
            r[lane]       = v0;
            r[lane + 32u] = v1;
            r[lane + 64u] = v2;
            r[lane + 96u] = v3;
            if (lane == 31u) r[128] = hc;
        }
        // prefetch next plane (independent of the barrier)
        float n0=0.f,n1=0.f,n2=0.f,n3=0.f,hn=0.f;
        if (x < ae && rowload) {
            const float* p = rowp + (size_t)(x + 1u) * PLANE;
            n0 = __ldg(p);      n1 = __ldg(p + 32);
            n2 = __ldg(p + 64); n3 = __ldg(p + 96);
            if (lane == 31u) hn = __ldg(p + 97);
        }
        __syncthreads();

        if (rowown) {
            if (x > as) {   // x-diffs for pair (x-1, x)
                s += fabsf(v0 - p0) + fabsf(v1 - p1)
                   + fabsf(v2 - p2) + fabsf(v3 - p3);
                if (halo31) s += fabsf(hc - hp);
            }
            if (x < ae || lastc) {   // y/z diffs owned for this plane
                const float* r  = sm[buf][wid];
                // z-diffs: neighbor z+1 from own smem row (incl. halo at 128)
                s += fabsf(r[lane + 1u]   - v0) + fabsf(r[lane + 33u] - v1)
                   + fabsf(r[lane + 65u]  - v2) + fabsf(r[lane + 97u] - v3);
                if (ypair) {   // y-diffs vs neighbor row from smem
                    const float* q = sm[buf][wid + 1u];
                    s += fabsf(q[lane]       - v0) + fabsf(q[lane + 32u] - v1)
                       + fabsf(q[lane + 64u] - v2) + fabsf(q[lane + 96u] - v3);
                    if (halo31) s += fabsf(q[128] - hc);
                }
            }
        }
        p0=v0; p1=v1; p2=v2; p3=v3; hp=hc;
        v0=n0; v1=n1; v2=n2; v3=n3; hc=hn;
        buf ^= 1u;
    }

    // ---- block reduction ----
    #pragma unroll
    for (int o = 16; o > 0; o >>= 1)
        s += __shfl_down_sync(0xffffffffu, s, o);

    __shared__ float    ws[WPB];
    __shared__ unsigned islast_s;
    if (lane == 0u) ws[wid] = s;
    __syncthreads();
    if (threadIdx.x == 0u) {
        float t = 0.f;
        #pragma unroll
        for (unsigned i = 0; i < WPB; ++i) t += ws[i];
        g_part[blockIdx.x] = (double)t;
        __threadfence();
        unsigned old = atomicAdd(&g_count, 1u);
        islast_s = (old == NBLOCKS - 1u) ? 1u : 0u;
    }
    __syncthreads();

    // ---- last block folds the partials (no second launch) ----
    if (islast_s) {
        double d = 0.0;
        for (unsigned i = threadIdx.x; i < NBLOCKS; i += 256u)
            d += g_part[i];
        __shared__ double dsm[256];
        dsm[threadIdx.x] = d;
        __syncthreads();
        #pragma unroll
        for (int st = 128; st > 0; st >>= 1) {
            if ((int)threadIdx.x < st) dsm[threadIdx.x] += dsm[threadIdx.x + st];
            __syncthreads();
        }
        if (threadIdx.x == 0u) {
            out[0] = (float)dsm[0];
            g_count = 0u;   // reset for next graph replay
        }
    }
}

extern "C" void kernel_launch(void* const* d_in, const int* in_sizes, int n_in,
                              void* d_out, int out_size) {
    const float* occ = (const float*)d_in[0];
    float* out = (float*)d_out;
    occ_main<<<NBLOCKS, 256>>>(occ, out);
}